// round 12
// baseline (speedup 1.0000x reference)
#include <cuda_runtime.h>

typedef unsigned int u32;

#define CC 256
#define NE 1024
#define CPG 128
#define ZQ_ELEMS (32*256*32*32)
#define LOSS_OFF ZQ_ELEMS
#define IDX_OFF  (ZQ_ELEMS + 3)
#define MEAN_DEN ((double)ZQ_ELEMS)

#define SSTR 260          // main smem row stride (floats)
#define TSTR 33           // transpose tile stride
#define SCREEN_T 2.5e-3f  // rigorous tf32 screen slack
#define MAXC 12

__device__ __align__(16) float g_codebook[NE*CC];
__device__ float  g_cnorm[NE];
__device__ __align__(16) float g_zt[32768*CC];   // token-major z
__device__ float  g_znorm[32768];
__device__ int    g_selg[32768];
__device__ double g_sqsum;

// m16n8k8 tf32 MMA (Ampere-class PTX; valid on sm_103 family target)
__device__ __forceinline__ void mma_tf32(float* d, u32 a0, u32 a1, u32 a2, u32 a3,
                                         u32 b0, u32 b1) {
    asm volatile(
        "mma.sync.aligned.m16n8k8.row.col.f32.tf32.tf32.f32 "
        "{%0,%1,%2,%3}, {%4,%5,%6,%7}, {%8,%9}, {%0,%1,%2,%3};"
        : "+f"(d[0]), "+f"(d[1]), "+f"(d[2]), "+f"(d[3])
        : "r"(a0), "r"(a1), "r"(a2), "r"(a3), "r"(b0), "r"(b1));
}

// ---------------------------------------------------------------------------
// Kernel K1 (fused prep + t1, launch_bounds(256,6) to keep regs <= 42 so the
// 1024 t1 blocks reach 6 blocks/SM):
//  blocks 0..127   : codebook = emb @ proj^T (sequential ascending-k fmaf
//                    chain per element — bit-exact), cnorm, zero loss.
//  blocks 128..1151: transpose z [B,C,H,W] -> g_zt [token][C] + reference-
//                    exact sequential znorm per token.
// ---------------------------------------------------------------------------
__global__ __launch_bounds__(256, 6)
void k1_kernel(const float* __restrict__ emb,
               const float* __restrict__ proj,
               const float* __restrict__ z) {
    __shared__ __align__(16) float sh[10568];    // union: 42.3 KB
    int tid  = threadIdx.x;

    if (blockIdx.x < 128) {
        // ================= prep half =================
        float* es_t = sh;                        // [k][j] 2048 floats
        float* pt   = sh + 2048;                 // [i][kk] 8448 floats
        float* part = sh + 2048 + 8448;          // [8][9]
        int lane = tid & 31;
        int warp = tid >> 5;
        int j0   = blockIdx.x * 8;

        for (int idx = tid; idx < 8*CC; idx += 256) {
            int j = idx >> 8, k = idx & 255;
            es_t[k*8 + j] = emb[j0*CC + idx];
        }

        float acc[8];
        #pragma unroll
        for (int j = 0; j < 8; j++) acc[j] = 0.f;

        const float4* p4 = (const float4*)proj;
        for (int kc = 0; kc < 8; kc++) {
            int k0 = kc*32;
            __syncthreads();
            #pragma unroll 2
            for (int it = 0; it < 8; it++) {
                int idx = tid + 256*it;
                int i = idx >> 3, kq = idx & 7;
                float4 v = p4[(size_t)i*64 + (k0 >> 2) + kq];
                pt[i*TSTR + kq*4 + 0] = v.x;
                pt[i*TSTR + kq*4 + 1] = v.y;
                pt[i*TSTR + kq*4 + 2] = v.z;
                pt[i*TSTR + kq*4 + 3] = v.w;
            }
            __syncthreads();
            #pragma unroll 8
            for (int kk = 0; kk < 32; kk++) {
                int k = k0 + kk;
                float pk = pt[tid*TSTR + kk];
                float4 e0 = *(const float4*)(es_t + k*8);
                float4 e1 = *(const float4*)(es_t + k*8 + 4);
                acc[0] = fmaf(e0.x, pk, acc[0]);
                acc[1] = fmaf(e0.y, pk, acc[1]);
                acc[2] = fmaf(e0.z, pk, acc[2]);
                acc[3] = fmaf(e0.w, pk, acc[3]);
                acc[4] = fmaf(e1.x, pk, acc[4]);
                acc[5] = fmaf(e1.y, pk, acc[5]);
                acc[6] = fmaf(e1.z, pk, acc[6]);
                acc[7] = fmaf(e1.w, pk, acc[7]);
            }
        }
        #pragma unroll
        for (int j = 0; j < 8; j++)
            g_codebook[(size_t)(j0 + j)*CC + tid] = acc[j];

        #pragma unroll
        for (int j = 0; j < 8; j++) {
            float v = acc[j]*acc[j];
            #pragma unroll
            for (int off = 16; off; off >>= 1)
                v += __shfl_down_sync(0xffffffffu, v, off);
            if (lane == 0) part[j*9 + warp] = v;
        }
        __syncthreads();
        if (tid < 8) {
            float s = 0.f;
            #pragma unroll
            for (int w = 0; w < 8; w++) s += part[tid*9 + w];
            g_cnorm[j0 + tid] = s;
        }
        if (blockIdx.x == 0 && tid == 0) g_sqsum = 0.0;
    } else {
        // ================= t1 half =================
        float* t = sh;                           // [c][w] 8448 floats
        int tb = blockIdx.x - 128;
        int b = tb >> 5, h = tb & 31;

        const float4* z4 = (const float4*)z;
        #pragma unroll 2
        for (int it = 0; it < 8; it++) {
            int idx = tid + 256*it;
            int c = idx >> 3, q = idx & 7;
            float4 v = z4[(size_t)b*65536 + (size_t)c*256 + h*8 + q];
            t[c*TSTR + q*4 + 0] = v.x;
            t[c*TSTR + q*4 + 1] = v.y;
            t[c*TSTR + q*4 + 2] = v.z;
            t[c*TSTR + q*4 + 3] = v.w;
        }
        __syncthreads();

        int base = b*1024 + h*32;
        if (tid < 32) {                           // znorm, exact chain
            float a = 0.f;
            #pragma unroll 8
            for (int c = 0; c < CC; c++) {
                float v = t[c*TSTR + tid];
                a = __fadd_rn(a, __fmul_rn(v, v));
            }
            g_znorm[base + tid] = a;
        }
        for (int w2 = 0; w2 < 32; w2++)           // token-major write
            g_zt[(size_t)(base + w2)*CC + tid] = t[tid*TSTR + w2];
    }
}

// ---------------------------------------------------------------------------
// Kernel 2: main.  Persistent 128 blocks (8 groups x 16) x 512 threads;
// each block stages its group codebook ONCE, then processes 4 chunks.
// Warp tile: 16 tokens x 32 codes (16 warps).  tf32 mma.sync screen ->
// candidates within SCREEN_T -> exact fp32 sequential-chain verify
// (reference-bit-exact, 8 thr/token).  Outputs idx + loss.
// ---------------------------------------------------------------------------
extern __shared__ float dsm[];

__global__ __launch_bounds__(512, 1)
void main_kernel(float* __restrict__ out) {
    float* Bs = dsm;                  // [128][SSTR] exact fp32 codebook
    float* zs = Bs + 128*SSTR;        // [64][SSTR]  exact fp32 z tokens

    __shared__ float  cn[CPG];
    __shared__ float  znm[64];
    __shared__ float  pmin[4][64];
    __shared__ float  thr_s[64];
    __shared__ int    ccnt[64];
    __shared__ int    cand[64][MAXC];
    __shared__ float  vb[8][64];
    __shared__ int    vi[8][64];

    int tid  = threadIdx.x;
    int lane = tid & 31;
    int warp = tid >> 5;              // 0..15
    int g    = blockIdx.x >> 4;
    int cq   = blockIdx.x & 15;
    int w0   = g * 4;

    // ---- stage group codebook + cn ONCE ----
    const float4* cb4 = (const float4*)(g_codebook + (size_t)g*CPG*CC);
    for (int i = tid; i < 8192; i += 512) {
        int j = i >> 6, c4 = i & 63;
        float4 v = cb4[(size_t)j*64 + c4];
        *(float4*)(Bs + j*SSTR + c4*4) = v;
    }
    if (tid < CPG) cn[tid] = g_cnorm[g*CPG + tid];

    int mw  = warp & 3;               // token 16-block
    int nq  = warp >> 2;              // code 32-block
    int gid = lane >> 2, tg = lane & 3;
    double accd = 0.0;

    for (int ci = 0; ci < 4; ci++) {
        int chunk = cq*4 + ci;

        // ---- per-chunk staging ----
        if (tid < 64) ccnt[tid] = 0;
        const float4* zt4 = (const float4*)g_zt;
        #pragma unroll
        for (int it = 0; it < 8; it++) {
            int idx = tid + 512*it;
            int t = idx >> 6, q = idx & 63;
            int gtok = (chunk*16 + (t >> 2))*32 + w0 + (t & 3);
            float4 v = zt4[(size_t)gtok*64 + q];
            *(float4*)(zs + t*SSTR + q*4) = v;
        }
        if (tid < 64) {
            int gtok = (chunk*16 + (tid >> 2))*32 + w0 + (tid & 3);
            znm[tid] = g_znorm[gtok];
        }
        __syncthreads();

        // ---- tf32 screen: warp = 16 tokens x 32 codes ----
        float acc[4][4];
        #pragma unroll
        for (int nt = 0; nt < 4; nt++)
            #pragma unroll
            for (int e = 0; e < 4; e++) acc[nt][e] = 0.f;

        const float* Ab = zs + (mw*16)*SSTR;
        #pragma unroll 2
        for (int kt = 0; kt < 32; kt++) {
            int k0 = kt*8;
            u32 a0 = __float_as_uint(Ab[gid*SSTR + k0 + tg]);
            u32 a1 = __float_as_uint(Ab[(gid+8)*SSTR + k0 + tg]);
            u32 a2 = __float_as_uint(Ab[gid*SSTR + k0 + tg + 4]);
            u32 a3 = __float_as_uint(Ab[(gid+8)*SSTR + k0 + tg + 4]);
            #pragma unroll
            for (int nt = 0; nt < 4; nt++) {
                const float* Bb = Bs + (nq*32 + nt*8 + gid)*SSTR + k0;
                u32 b0 = __float_as_uint(Bb[tg]);
                u32 b1 = __float_as_uint(Bb[tg+4]);
                mma_tf32(acc[nt], a0, a1, a2, a3, b0, b1);
            }
        }

        // ---- screen scores: s = cn[n] - 2*dot ----
        #pragma unroll
        for (int nt = 0; nt < 4; nt++)
            #pragma unroll
            for (int e = 0; e < 4; e++) {
                int n = nq*32 + nt*8 + 2*tg + (e & 1);
                acc[nt][e] = fmaf(-2.f, acc[nt][e], cn[n]);
            }

        float mi0 = 3.4e38f, mi1 = 3.4e38f;
        #pragma unroll
        for (int nt = 0; nt < 4; nt++) {
            mi0 = fminf(mi0, fminf(acc[nt][0], acc[nt][1]));
            mi1 = fminf(mi1, fminf(acc[nt][2], acc[nt][3]));
        }
        mi0 = fminf(mi0, __shfl_xor_sync(0xffffffffu, mi0, 1));
        mi0 = fminf(mi0, __shfl_xor_sync(0xffffffffu, mi0, 2));
        mi1 = fminf(mi1, __shfl_xor_sync(0xffffffffu, mi1, 1));
        mi1 = fminf(mi1, __shfl_xor_sync(0xffffffffu, mi1, 2));
        if (tg == 0) {
            pmin[nq][mw*16 + gid]     = mi0;
            pmin[nq][mw*16 + gid + 8] = mi1;
        }
        __syncthreads();
        if (tid < 64)
            thr_s[tid] = fminf(fminf(pmin[0][tid], pmin[1][tid]),
                               fminf(pmin[2][tid], pmin[3][tid])) + SCREEN_T;
        __syncthreads();

        // ---- candidate collection ----
        #pragma unroll
        for (int nt = 0; nt < 4; nt++)
            #pragma unroll
            for (int e = 0; e < 4; e++) {
                int token = mw*16 + gid + ((e >> 1) ? 8 : 0);
                if (acc[nt][e] <= thr_s[token]) {
                    int s = atomicAdd(&ccnt[token], 1);
                    if (s < MAXC) cand[token][s] = nq*32 + nt*8 + 2*tg + (e & 1);
                }
            }
        __syncthreads();

        // ---- exact verify (reference-bit-exact), 8 threads per token ----
        {
            int t = tid & 63, q = tid >> 6;      // q = 0..7
            float best = 3.4e38f;
            int   bj   = 1 << 30;
            float zn = znm[t];
            const float* zr = zs + t*SSTR;
            int nc = ccnt[t];
            if (nc <= MAXC) {
                for (int i = q; i < nc; i += 8) {
                    int j = cand[t][i];
                    const float* cr = Bs + j*SSTR;
                    float a = 0.f;
                    #pragma unroll 8
                    for (int c = 0; c < CC; c++) a = fmaf(cr[c], zr[c], a);
                    float d = __fsub_rn(__fadd_rn(zn, cn[j]), __fadd_rn(a, a));
                    if (d < best || (d == best && j < bj)) { best = d; bj = j; }
                }
            } else {
                for (int j = q; j < 128; j += 8) {
                    const float* cr = Bs + j*SSTR;
                    float a = 0.f;
                    #pragma unroll 8
                    for (int c = 0; c < CC; c++) a = fmaf(cr[c], zr[c], a);
                    float d = __fsub_rn(__fadd_rn(zn, cn[j]), __fadd_rn(a, a));
                    if (d < best || (d == best && j < bj)) { best = d; bj = j; }
                }
            }
            vb[q][t] = best; vi[q][t] = bj;
        }
        __syncthreads();

        // ---- final select + loss accumulation (d_best == sum_c (zq-z)^2) ----
        double tok_d = 0.0;
        if (tid < 64) {
            float best = vb[0][tid]; int bj = vi[0][tid];
            #pragma unroll
            for (int q = 1; q < 8; q++) {
                float d = vb[q][tid]; int j = vi[q][tid];
                if (d < best || (d == best && j < bj)) { best = d; bj = j; }
            }
            int gtok = (chunk*16 + (tid >> 2))*32 + w0 + (tid & 3);
            int gcode = g*CPG + bj;
            g_selg[gtok] = gcode;
            out[IDX_OFF + gtok] = (float)gcode;
            tok_d = (double)best;
        }
        #pragma unroll
        for (int off = 16; off; off >>= 1)
            tok_d += __shfl_down_sync(0xffffffffu, tok_d, off);
        if (warp < 2 && lane == 0) accd += tok_d;
        __syncthreads();   // protect zs/ccnt/pmin/vb reuse next chunk
    }

    if (warp < 2 && lane == 0) atomicAdd(&g_sqsum, accd);
}

// ---------------------------------------------------------------------------
// Kernel T2: gather zq rows from codebook via sel, write out[B,C,H,W]
// coalesced.  512 threads/block.  Block 0 writes losses (g_sqsum final by
// stream order).
// ---------------------------------------------------------------------------
__global__ __launch_bounds__(512)
void t2_kernel(float* __restrict__ out) {
    __shared__ float t[256*TSTR];                // [c][w]
    __shared__ int   sel_s[32];
    int tid  = threadIdx.x;
    int b = blockIdx.x >> 5, h = blockIdx.x & 31;
    int base = b*1024 + h*32;

    if (blockIdx.x == 0 && tid == 0) {
        double M = g_sqsum / MEAN_DEN;
        out[LOSS_OFF + 0] = (float)(1.25 * M);
        out[LOSS_OFF + 1] = (float)(0.25 * M);
        out[LOSS_OFF + 2] = (float)M;
    }

    if (tid < 32) sel_s[tid] = g_selg[base + tid];
    __syncthreads();

    {
        int c = tid & 255, half = tid >> 8;
        const float* cb = g_codebook + c;
        #pragma unroll
        for (int i = 0; i < 16; i++) {
            int w2 = half*16 + i;
            t[c*TSTR + w2] = cb[(size_t)sel_s[w2]*CC];
        }
    }
    __syncthreads();

    float4* o4 = (float4*)out;
    #pragma unroll
    for (int it = 0; it < 4; it++) {
        int idx = tid + 512*it;
        int c = idx >> 3, q = idx & 7;
        float4 v;
        v.x = t[c*TSTR + q*4 + 0];
        v.y = t[c*TSTR + q*4 + 1];
        v.z = t[c*TSTR + q*4 + 2];
        v.w = t[c*TSTR + q*4 + 3];
        o4[(size_t)b*65536 + (size_t)c*256 + h*8 + q] = v;
    }
}

// ---------------------------------------------------------------------------
extern "C" void kernel_launch(void* const* d_in, const int* in_sizes, int n_in,
                              void* d_out, int out_size) {
    const float *z = nullptr, *emb = nullptr, *proj = nullptr;
    for (int i = 0; i < n_in; i++) {
        if (in_sizes[i] == ZQ_ELEMS)      z    = (const float*)d_in[i];
        else if (in_sizes[i] == NE*CC)    emb  = (const float*)d_in[i];
        else if (in_sizes[i] == CC*CC)    proj = (const float*)d_in[i];
    }
    float* out = (float*)d_out;

    const int SMEM_BYTES = (128*SSTR + 64*SSTR) * (int)sizeof(float);  // 199,680
    cudaFuncSetAttribute(main_kernel,
                         cudaFuncAttributeMaxDynamicSharedMemorySize, SMEM_BYTES);

    k1_kernel<<<1152, 256>>>(emb, proj, z);
    main_kernel<<<128, 512, SMEM_BYTES>>>(out);
    t2_kernel<<<1024, 512>>>(out);
}

// round 13
// speedup vs baseline: 1.0906x; 1.0906x over previous
#include <cuda_runtime.h>

typedef unsigned int u32;

#define CC 256
#define NE 1024
#define CPG 128
#define ZQ_ELEMS (32*256*32*32)
#define LOSS_OFF ZQ_ELEMS
#define IDX_OFF  (ZQ_ELEMS + 3)
#define MEAN_DEN ((double)ZQ_ELEMS)

#define SSTR 260          // main smem row stride (floats)
#define TSTR 33           // transpose tile stride
#define SCREEN_T 2.5e-3f  // rigorous tf32 screen slack
#define MAXC 12

__device__ __align__(16) float g_codebook[NE*CC];
__device__ float  g_cnorm[NE];
__device__ __align__(16) float g_zt[32768*CC];   // token-major z
__device__ float  g_znorm[32768];
__device__ int    g_selg[32768];
__device__ double g_sqsum;

// m16n8k8 tf32 MMA (Ampere-class PTX; valid on sm_103 family target)
__device__ __forceinline__ void mma_tf32(float* d, u32 a0, u32 a1, u32 a2, u32 a3,
                                         u32 b0, u32 b1) {
    asm volatile(
        "mma.sync.aligned.m16n8k8.row.col.f32.tf32.tf32.f32 "
        "{%0,%1,%2,%3}, {%4,%5,%6,%7}, {%8,%9}, {%0,%1,%2,%3};"
        : "+f"(d[0]), "+f"(d[1]), "+f"(d[2]), "+f"(d[3])
        : "r"(a0), "r"(a1), "r"(a2), "r"(a3), "r"(b0), "r"(b1));
}

// ---------------------------------------------------------------------------
// Kernel K1 (fused prep + t1; both branches kept at a similar natural
// register footprint — no launch_bounds cap, no spills):
//  blocks 0..255   : codebook = emb @ proj^T, 4 rows/block (sequential
//                    ascending-k fmaf chain per element — bit-exact),
//                    cnorm, zero loss.
//  blocks 256..1279: transpose z [B,C,H,W] -> g_zt [token][C] + reference-
//                    exact sequential znorm per token.
// ---------------------------------------------------------------------------
__global__ __launch_bounds__(256)
void k1_kernel(const float* __restrict__ emb,
               const float* __restrict__ proj,
               const float* __restrict__ z) {
    __shared__ __align__(16) float sh[9512];     // union: 38.0 KB
    int tid  = threadIdx.x;

    if (blockIdx.x < 256) {
        // ================= prep half (4 rows/block) =================
        float* es_t = sh;                        // [k][j] 1024 floats
        float* pt   = sh + 1024;                 // [i][kk] 8448 floats
        float* part = sh + 1024 + 8448;          // [4][9]
        int lane = tid & 31;
        int warp = tid >> 5;
        int j0   = blockIdx.x * 4;

        for (int idx = tid; idx < 4*CC; idx += 256) {
            int j = idx >> 8, k = idx & 255;
            es_t[k*4 + j] = emb[j0*CC + idx];
        }

        float acc[4];
        #pragma unroll
        for (int j = 0; j < 4; j++) acc[j] = 0.f;

        const float4* p4 = (const float4*)proj;
        for (int kc = 0; kc < 8; kc++) {
            int k0 = kc*32;
            __syncthreads();
            #pragma unroll
            for (int it = 0; it < 8; it++) {
                int idx = tid + 256*it;
                int i = idx >> 3, kq = idx & 7;
                float4 v = p4[(size_t)i*64 + (k0 >> 2) + kq];
                pt[i*TSTR + kq*4 + 0] = v.x;
                pt[i*TSTR + kq*4 + 1] = v.y;
                pt[i*TSTR + kq*4 + 2] = v.z;
                pt[i*TSTR + kq*4 + 3] = v.w;
            }
            __syncthreads();
            #pragma unroll 8
            for (int kk = 0; kk < 32; kk++) {
                int k = k0 + kk;
                float pk = pt[tid*TSTR + kk];
                float4 e = *(const float4*)(es_t + k*4);
                acc[0] = fmaf(e.x, pk, acc[0]);
                acc[1] = fmaf(e.y, pk, acc[1]);
                acc[2] = fmaf(e.z, pk, acc[2]);
                acc[3] = fmaf(e.w, pk, acc[3]);
            }
        }
        #pragma unroll
        for (int j = 0; j < 4; j++)
            g_codebook[(size_t)(j0 + j)*CC + tid] = acc[j];

        #pragma unroll
        for (int j = 0; j < 4; j++) {
            float v = acc[j]*acc[j];
            #pragma unroll
            for (int off = 16; off; off >>= 1)
                v += __shfl_down_sync(0xffffffffu, v, off);
            if (lane == 0) part[j*9 + warp] = v;
        }
        __syncthreads();
        if (tid < 4) {
            float s = 0.f;
            #pragma unroll
            for (int w = 0; w < 8; w++) s += part[tid*9 + w];
            g_cnorm[j0 + tid] = s;
        }
        if (blockIdx.x == 0 && tid == 0) g_sqsum = 0.0;
    } else {
        // ================= t1 half =================
        float* t = sh;                           // [c][w] 8448 floats
        int tb = blockIdx.x - 256;
        int b = tb >> 5, h = tb & 31;

        const float4* z4 = (const float4*)z;
        #pragma unroll
        for (int it = 0; it < 8; it++) {
            int idx = tid + 256*it;
            int c = idx >> 3, q = idx & 7;
            float4 v = z4[(size_t)b*65536 + (size_t)c*256 + h*8 + q];
            t[c*TSTR + q*4 + 0] = v.x;
            t[c*TSTR + q*4 + 1] = v.y;
            t[c*TSTR + q*4 + 2] = v.z;
            t[c*TSTR + q*4 + 3] = v.w;
        }
        __syncthreads();

        int base = b*1024 + h*32;
        if (tid < 32) {                           // znorm, exact chain
            float a = 0.f;
            #pragma unroll 8
            for (int c = 0; c < CC; c++) {
                float v = t[c*TSTR + tid];
                a = __fadd_rn(a, __fmul_rn(v, v));
            }
            g_znorm[base + tid] = a;
        }
        for (int w2 = 0; w2 < 32; w2++)           // token-major write
            g_zt[(size_t)(base + w2)*CC + tid] = t[tid*TSTR + w2];
    }
}

// ---------------------------------------------------------------------------
// Kernel 2: main.  Persistent 128 blocks (8 groups x 16) x 256 threads;
// each block stages its group codebook ONCE, then processes 4 chunks.
// tf32 mma.sync screen -> candidates within SCREEN_T -> exact fp32
// sequential-chain verify (reference-bit-exact).  Outputs idx + loss.
// ---------------------------------------------------------------------------
extern __shared__ float dsm[];

__global__ __launch_bounds__(256, 1)
void main_kernel(float* __restrict__ out) {
    float* Bs = dsm;                  // [128][SSTR] exact fp32 codebook
    float* zs = Bs + 128*SSTR;        // [64][SSTR]  exact fp32 z tokens

    __shared__ float  cn[CPG];
    __shared__ float  znm[64];
    __shared__ float  pmin[2][64];
    __shared__ float  thr_s[64];
    __shared__ int    ccnt[64];
    __shared__ int    cand[64][MAXC];
    __shared__ float  vb[4][64];
    __shared__ int    vi[4][64];

    int tid  = threadIdx.x;
    int lane = tid & 31;
    int warp = tid >> 5;
    int g    = blockIdx.x >> 4;
    int cq   = blockIdx.x & 15;
    int w0   = g * 4;

    // ---- stage group codebook + cn ONCE ----
    const float4* cb4 = (const float4*)(g_codebook + (size_t)g*CPG*CC);
    for (int i = tid; i < 8192; i += 256) {
        int j = i >> 6, c4 = i & 63;
        float4 v = cb4[(size_t)j*64 + c4];
        *(float4*)(Bs + j*SSTR + c4*4) = v;
    }
    if (tid < CPG) cn[tid] = g_cnorm[g*CPG + tid];

    int mw  = warp & 3;
    int nh  = warp >> 2;
    int gid = lane >> 2, tg = lane & 3;
    double accd = 0.0;

    for (int ci = 0; ci < 4; ci++) {
        int chunk = cq*4 + ci;

        // ---- per-chunk staging ----
        if (tid < 64) ccnt[tid] = 0;
        const float4* zt4 = (const float4*)g_zt;
        #pragma unroll
        for (int it = 0; it < 16; it++) {
            int idx = tid + 256*it;
            int t = idx >> 6, q = idx & 63;
            int gtok = (chunk*16 + (t >> 2))*32 + w0 + (t & 3);
            float4 v = zt4[(size_t)gtok*64 + q];
            *(float4*)(zs + t*SSTR + q*4) = v;
        }
        if (tid < 64) {
            int gtok = (chunk*16 + (tid >> 2))*32 + w0 + (tid & 3);
            znm[tid] = g_znorm[gtok];
        }
        __syncthreads();

        // ---- tf32 screen ----
        float acc[8][4];
        #pragma unroll
        for (int nt = 0; nt < 8; nt++)
            #pragma unroll
            for (int e = 0; e < 4; e++) acc[nt][e] = 0.f;

        const float* Ab = zs + (mw*16)*SSTR;
        #pragma unroll 2
        for (int kt = 0; kt < 32; kt++) {
            int k0 = kt*8;
            u32 a0 = __float_as_uint(Ab[gid*SSTR + k0 + tg]);
            u32 a1 = __float_as_uint(Ab[(gid+8)*SSTR + k0 + tg]);
            u32 a2 = __float_as_uint(Ab[gid*SSTR + k0 + tg + 4]);
            u32 a3 = __float_as_uint(Ab[(gid+8)*SSTR + k0 + tg + 4]);
            #pragma unroll
            for (int nt = 0; nt < 8; nt++) {
                const float* Bb = Bs + (nh*64 + nt*8 + gid)*SSTR + k0;
                u32 b0 = __float_as_uint(Bb[tg]);
                u32 b1 = __float_as_uint(Bb[tg+4]);
                mma_tf32(acc[nt], a0, a1, a2, a3, b0, b1);
            }
        }

        // ---- screen scores: s = cn[n] - 2*dot ----
        #pragma unroll
        for (int nt = 0; nt < 8; nt++)
            #pragma unroll
            for (int e = 0; e < 4; e++) {
                int n = nh*64 + nt*8 + 2*tg + (e & 1);
                acc[nt][e] = fmaf(-2.f, acc[nt][e], cn[n]);
            }

        float mi0 = 3.4e38f, mi1 = 3.4e38f;
        #pragma unroll
        for (int nt = 0; nt < 8; nt++) {
            mi0 = fminf(mi0, fminf(acc[nt][0], acc[nt][1]));
            mi1 = fminf(mi1, fminf(acc[nt][2], acc[nt][3]));
        }
        mi0 = fminf(mi0, __shfl_xor_sync(0xffffffffu, mi0, 1));
        mi0 = fminf(mi0, __shfl_xor_sync(0xffffffffu, mi0, 2));
        mi1 = fminf(mi1, __shfl_xor_sync(0xffffffffu, mi1, 1));
        mi1 = fminf(mi1, __shfl_xor_sync(0xffffffffu, mi1, 2));
        if (tg == 0) {
            pmin[nh][mw*16 + gid]     = mi0;
            pmin[nh][mw*16 + gid + 8] = mi1;
        }
        __syncthreads();
        if (tid < 64) thr_s[tid] = fminf(pmin[0][tid], pmin[1][tid]) + SCREEN_T;
        __syncthreads();

        // ---- candidate collection ----
        #pragma unroll
        for (int nt = 0; nt < 8; nt++)
            #pragma unroll
            for (int e = 0; e < 4; e++) {
                int token = mw*16 + gid + ((e >> 1) ? 8 : 0);
                if (acc[nt][e] <= thr_s[token]) {
                    int s = atomicAdd(&ccnt[token], 1);
                    if (s < MAXC) cand[token][s] = nh*64 + nt*8 + 2*tg + (e & 1);
                }
            }
        __syncthreads();

        // ---- exact verify (reference-bit-exact), 4 threads per token ----
        {
            int t = tid & 63, q = tid >> 6;
            float best = 3.4e38f;
            int   bj   = 1 << 30;
            float zn = znm[t];
            const float* zr = zs + t*SSTR;
            int nc = ccnt[t];
            if (nc <= MAXC) {
                for (int i = q; i < nc; i += 4) {
                    int j = cand[t][i];
                    const float* cr = Bs + j*SSTR;
                    float a = 0.f;
                    #pragma unroll 8
                    for (int c = 0; c < CC; c++) a = fmaf(cr[c], zr[c], a);
                    float d = __fsub_rn(__fadd_rn(zn, cn[j]), __fadd_rn(a, a));
                    if (d < best || (d == best && j < bj)) { best = d; bj = j; }
                }
            } else {
                for (int j = q; j < 128; j += 4) {
                    const float* cr = Bs + j*SSTR;
                    float a = 0.f;
                    #pragma unroll 8
                    for (int c = 0; c < CC; c++) a = fmaf(cr[c], zr[c], a);
                    float d = __fsub_rn(__fadd_rn(zn, cn[j]), __fadd_rn(a, a));
                    if (d < best || (d == best && j < bj)) { best = d; bj = j; }
                }
            }
            vb[q][t] = best; vi[q][t] = bj;
        }
        __syncthreads();

        // ---- final select + loss accumulation ----
        double tok_d = 0.0;
        if (tid < 64) {
            float best = vb[0][tid]; int bj = vi[0][tid];
            #pragma unroll
            for (int q = 1; q < 4; q++) {
                float d = vb[q][tid]; int j = vi[q][tid];
                if (d < best || (d == best && j < bj)) { best = d; bj = j; }
            }
            int gtok = (chunk*16 + (tid >> 2))*32 + w0 + (tid & 3);
            int gcode = g*CPG + bj;
            g_selg[gtok] = gcode;
            out[IDX_OFF + gtok] = (float)gcode;
            tok_d = (double)best;
        }
        #pragma unroll
        for (int off = 16; off; off >>= 1)
            tok_d += __shfl_down_sync(0xffffffffu, tok_d, off);
        if (warp < 2 && lane == 0) accd += tok_d;
        __syncthreads();   // protect zs/ccnt/pmin/vb reuse next chunk
    }

    if (warp < 2 && lane == 0) atomicAdd(&g_sqsum, accd);
}

// ---------------------------------------------------------------------------
// Kernel T2: gather zq rows from codebook via sel, write out[B,C,H,W]
// coalesced.  512 threads/block.  Block 0 writes losses (g_sqsum final by
// stream order).
// ---------------------------------------------------------------------------
__global__ __launch_bounds__(512)
void t2_kernel(float* __restrict__ out) {
    __shared__ float t[256*TSTR];                // [c][w]
    __shared__ int   sel_s[32];
    int tid  = threadIdx.x;
    int b = blockIdx.x >> 5, h = blockIdx.x & 31;
    int base = b*1024 + h*32;

    if (blockIdx.x == 0 && tid == 0) {
        double M = g_sqsum / MEAN_DEN;
        out[LOSS_OFF + 0] = (float)(1.25 * M);
        out[LOSS_OFF + 1] = (float)(0.25 * M);
        out[LOSS_OFF + 2] = (float)M;
    }

    if (tid < 32) sel_s[tid] = g_selg[base + tid];
    __syncthreads();

    {
        int c = tid & 255, half = tid >> 8;
        const float* cb = g_codebook + c;
        #pragma unroll
        for (int i = 0; i < 16; i++) {
            int w2 = half*16 + i;
            t[c*TSTR + w2] = cb[(size_t)sel_s[w2]*CC];
        }
    }
    __syncthreads();

    float4* o4 = (float4*)out;
    #pragma unroll
    for (int it = 0; it < 4; it++) {
        int idx = tid + 512*it;
        int c = idx >> 3, q = idx & 7;
        float4 v;
        v.x = t[c*TSTR + q*4 + 0];
        v.y = t[c*TSTR + q*4 + 1];
        v.z = t[c*TSTR + q*4 + 2];
        v.w = t[c*TSTR + q*4 + 3];
        o4[(size_t)b*65536 + (size_t)c*256 + h*8 + q] = v;
    }
}

// ---------------------------------------------------------------------------
extern "C" void kernel_launch(void* const* d_in, const int* in_sizes, int n_in,
                              void* d_out, int out_size) {
    const float *z = nullptr, *emb = nullptr, *proj = nullptr;
    for (int i = 0; i < n_in; i++) {
        if (in_sizes[i] == ZQ_ELEMS)      z    = (const float*)d_in[i];
        else if (in_sizes[i] == NE*CC)    emb  = (const float*)d_in[i];
        else if (in_sizes[i] == CC*CC)    proj = (const float*)d_in[i];
    }
    float* out = (float*)d_out;

    const int SMEM_BYTES = (128*SSTR + 64*SSTR) * (int)sizeof(float);  // 199,680
    cudaFuncSetAttribute(main_kernel,
                         cudaFuncAttributeMaxDynamicSharedMemorySize, SMEM_BYTES);

    k1_kernel<<<1280, 256>>>(emb, proj, z);
    main_kernel<<<128, 256, SMEM_BYTES>>>(out);
    t2_kernel<<<1024, 512>>>(out);
}